// round 11
// baseline (speedup 1.0000x reference)
#include <cuda_runtime.h>
#include <cstdint>

// Problem constants (N=32768, D=64, K=64 per reference)
#define NPTS 32768
#define DIM 64
#define NK 64
#define ROWS_PER_BLOCK 64
#define NTHREADS 64            // 2 warps: warp0 k[0,32), warp1 k[32,64)
#define NBLOCKS (NPTS / ROWS_PER_BLOCK)   // 512

// Scratch (allocation-free rule: __device__ globals)
__device__ __align__(16) float d_negmuP[NK * DIM];  // -(means_k @ P_k), [K,D]
__device__ float d_Cpart[NK];                       // C without stick-breaking cumsum
__device__ float d_sdb[NK];                         // digamma(b)-digamma(a+b)

// ---------------------------------------------------------------------------
// NaN-proof helpers (identity on valid inputs).
// ---------------------------------------------------------------------------
static __device__ __forceinline__ double safe_log(double v) {
    v = fabs(v);
    if (v < 1e-300) v = 1e-300;
    return log(v);
}

// digamma in double; recurrence as independent divides (bit-identical order).
static __device__ __forceinline__ double digamma_d(double x) {
    if (!(x > 1e-6)) x = 1e-6;
    double r = 0.0;
    const double m = (x < 6.0) ? ceil(6.0 - x) : 0.0;   // <= 6 for x >= 0.5
#pragma unroll
    for (int j = 0; j < 6; ++j)
        if ((double)j < m) r -= 1.0 / (x + (double)j);
    x += m;
    const double inv  = 1.0 / x;
    const double inv2 = inv * inv;
    const double s = inv2 * (1.0 / 12.0
                   - inv2 * (1.0 / 120.0
                   - inv2 * (1.0 / 252.0
                   - inv2 * (1.0 / 240.0))));
    return r + log(x) - 0.5 * inv - s;
}

// ---------------------------------------------------------------------------
// Prep: 64 blocks (cluster k) x 64 threads (dimension i).
// ---------------------------------------------------------------------------
__global__ void bgm_prep_a(const float* __restrict__ means,
                           const float* __restrict__ P,
                           const float* __restrict__ wc,
                           const float* __restrict__ v64a,
                           const float* __restrict__ v64b) {
    const int k = blockIdx.x;
    const int i = threadIdx.x;
    __shared__ double sd[NK];

    const bool a_is_dof = (v64a[0] > 32.0f);   // dof in [65,114], mp in (0.5,10]
    const float* __restrict__ dof = a_is_dof ? v64a : v64b;
    const float* __restrict__ mp  = a_is_dof ? v64b : v64a;

    const double dofk = (double)dof[k];

    const double t  = digamma_d(0.5 * (dofk - (double)i));
    const double lg = safe_log((double)P[k * DIM * DIM + i * DIM + i]);
    sd[i] = lg + 0.5 * t;
    __syncthreads();

    {   // negmuP column i
        float s = 0.0f;
        for (int d = 0; d < DIM; ++d)
            s = fmaf(means[k * DIM + d], P[k * DIM * DIM + d * DIM + i], s);
        d_negmuP[k * DIM + i] = -s;
    }

    for (int off = 32; off > 0; off >>= 1) {
        if (i < off) sd[i] += sd[i + off];
        __syncthreads();
    }

    if (i == 0) {
        double mpk = (double)mp[k];
        if (!(mpk > 1e-6)) mpk = 1e-6;
        const double a  = (double)wc[k];
        const double b  = (double)wc[NK + k];
        const double ds = digamma_d(a + b);
        const double dga = digamma_d(a);
        const double dgb = digamma_d(b);
        double C = sd[0]
                 + 0.5 * (double)DIM * 0.69314718055994530942   // +0.5*D*log2
                 - 0.5 * (double)DIM * 1.8378770664093454836    // -0.5*D*log(2pi)
                 - 0.5 * (double)DIM * safe_log(dofk)
                 - 0.5 * (double)DIM / mpk
                 + dga - ds;
        d_Cpart[k] = (float)C;
        d_sdb[k]   = (float)(dgb - ds);
    }
}

// ---------------------------------------------------------------------------
// Packed f32x2 helpers (FFMA2 SASS — 2x scalar FFMA throughput on sm_103a)
// ---------------------------------------------------------------------------
static __device__ __forceinline__ unsigned long long ff2(
    unsigned long long a, unsigned long long b, unsigned long long c) {
    unsigned long long d;
    asm("fma.rn.f32x2 %0, %1, %2, %3;" : "=l"(d) : "l"(a), "l"(b), "l"(c));
    return d;
}
static __device__ __forceinline__ unsigned long long fadd2(
    unsigned long long a, unsigned long long b) {
    unsigned long long d;
    asm("add.rn.f32x2 %0, %1, %2;" : "=l"(d) : "l"(a), "l"(b));
    return d;
}
static __device__ __forceinline__ unsigned long long pack2(float x) {
    unsigned long long d;
    asm("mov.b64 %0, {%1, %1};" : "=l"(d) : "f"(x));
    return d;
}
static __device__ __forceinline__ void unpack2(unsigned long long v, float& lo, float& hi) {
    asm("mov.b64 {%0, %1}, %2;" : "=f"(lo), "=f"(hi) : "l"(v));
}

// ---------------------------------------------------------------------------
// Main kernel: 512 blocks x 64 threads (2 warps). 64 rows/block.
// Warp w handles ALL 64 rows (lane l -> rows l, l+32) for k in [32w, 32w+32).
// P is read straight from GLOBAL with uniform-address LDG.128 (L1-resident,
// 1 wavefront/load) — no smem staging, no cp.async, no per-k barriers.
// P_k upper-triangular: e-quarter q needs only d < 16(q+1) (bit-exact skip).
// Final merge of the two k-halves via smem, strict-> (first-max semantics).
// OUTPUT: float32 index values.
// ---------------------------------------------------------------------------
__global__ __launch_bounds__(NTHREADS) void bgm_argmax_kernel(
    const float* __restrict__ X,
    const float* __restrict__ P,
    float* __restrict__ out) {

    __shared__ __align__(16) float Xsm[ROWS_PER_BLOCK * (DIM + 1)];   // 16.6 KB
    __shared__ float Csm[NK];
    __shared__ float Sdb[NK];
    __shared__ float bestHi[ROWS_PER_BLOCK];
    __shared__ int   argHi[ROWS_PER_BLOCK];

    const int tid  = threadIdx.x;
    const int wid  = tid >> 5;
    const int lane = tid & 31;
    const int row0 = blockIdx.x * ROWS_PER_BLOCK;

    // Stage X tile: 64 rows -> 1024 float4, 16 per thread.
    {
        const float4* __restrict__ Xg =
            reinterpret_cast<const float4*>(X + row0 * DIM);
        for (int i = tid; i < ROWS_PER_BLOCK * (DIM / 4); i += NTHREADS) {
            const float4 v = Xg[i];
            const int r = i >> 4;
            const int c = (i & 15) << 2;
            float* dst = &Xsm[r * (DIM + 1) + c];
            dst[0] = v.x; dst[1] = v.y; dst[2] = v.z; dst[3] = v.w;
        }
    }
    Sdb[tid] = d_sdb[tid];           // NTHREADS == NK
    __syncthreads();
    {   // Stick-breaking exclusive cumsum, bit-identical sequential fp32 order.
        float pre = 0.0f;
        for (int j = 0; j < tid; ++j) pre += Sdb[j];
        Csm[tid] = d_Cpart[tid] + pre;
    }
    __syncthreads();

    const int kbase = wid << 5;                  // 0 or 32
    const int xb0 = lane * (DIM + 1);            // row lane
    const int xb1 = (lane + 32) * (DIM + 1);     // row lane+32
    float best0 = __int_as_float(0xff800000u), best1 = best0;
    int   arg0 = kbase, arg1 = kbase;

    const ulonglong2* __restrict__ nmAll =
        reinterpret_cast<const ulonglong2*>(d_negmuP);

    for (int kk = 0; kk < 32; ++kk) {
        const int k = kbase + kk;
        const ulonglong2* __restrict__ Pk =
            reinterpret_cast<const ulonglong2*>(P + k * DIM * DIM);
        unsigned long long s0 = 0ULL, s1 = 0ULL;   // running sq as f32x2 pairs

#pragma unroll
        for (int q = 0; q < 4; ++q) {   // e-quarter [16q, 16q+16)
            unsigned long long a0[8], a1[8];
#pragma unroll
            for (int j = 0; j < 8; ++j) { a0[j] = 0ULL; a1[j] = 0ULL; }

            const int dmax = 16 * (q + 1);        // triangular bound
#pragma unroll 4
            for (int d = 0; d < dmax; ++d) {
                const unsigned long long x0 = pack2(Xsm[xb0 + d]);
                const unsigned long long x1 = pack2(Xsm[xb1 + d]);
                const ulonglong2* __restrict__ pr = Pk + (d << 4) + (q << 2);
#pragma unroll
                for (int j = 0; j < 4; ++j) {
                    const ulonglong2 p = pr[j];   // LDG.128 uniform (L1 hit)
                    a0[2 * j]     = ff2(x0, p.x, a0[2 * j]);
                    a0[2 * j + 1] = ff2(x0, p.y, a0[2 * j + 1]);
                    a1[2 * j]     = ff2(x1, p.x, a1[2 * j]);
                    a1[2 * j + 1] = ff2(x1, p.y, a1[2 * j + 1]);
                }
            }

            // Quarter epilogue: s += (acc + negmuP_quarter)^2
            const ulonglong2* __restrict__ nm = nmAll + (k << 4) + (q << 2);
#pragma unroll
            for (int j = 0; j < 4; ++j) {
                const ulonglong2 m = nm[j];
                const unsigned long long e0a = fadd2(a0[2 * j],     m.x);
                const unsigned long long e0b = fadd2(a0[2 * j + 1], m.y);
                const unsigned long long e1a = fadd2(a1[2 * j],     m.x);
                const unsigned long long e1b = fadd2(a1[2 * j + 1], m.y);
                s0 = ff2(e0a, e0a, s0);
                s0 = ff2(e0b, e0b, s0);
                s1 = ff2(e1a, e1a, s1);
                s1 = ff2(e1b, e1b, s1);
            }
        }

        float l0, h0, l1, h1;
        unpack2(s0, l0, h0);
        unpack2(s1, l1, h1);
        const float sq0 = l0 + h0;
        const float sq1 = l1 + h1;

        const float Ck = Csm[k];
        const float w0 = fmaf(-0.5f, sq0, Ck);
        const float w1 = fmaf(-0.5f, sq1, Ck);
        if (w0 > best0) { best0 = w0; arg0 = k; }
        if (w1 > best1) { best1 = w1; arg1 = k; }
    }

    // Merge the two k-halves (hi wins only if strictly greater -> first-max).
    if (wid == 1) {
        bestHi[lane]      = best0;  argHi[lane]      = arg0;
        bestHi[lane + 32] = best1;  argHi[lane + 32] = arg1;
    }
    __syncthreads();
    if (wid == 0) {
        int a0f = arg0, a1f = arg1;
        if (bestHi[lane]      > best0) a0f = argHi[lane];
        if (bestHi[lane + 32] > best1) a1f = argHi[lane + 32];
        out[row0 + lane]      = (float)a0f;
        out[row0 + lane + 32] = (float)a1f;
    }
}

// ---------------------------------------------------------------------------
// Launch. Inputs identified by ELEMENT COUNT; dof/mp disambiguated on device.
// Output: float32 index values [N].
// ---------------------------------------------------------------------------
extern "C" void kernel_launch(void* const* d_in, const int* in_sizes, int n_in,
                              void* d_out, int out_size) {
    (void)out_size;
    const float* X     = nullptr;
    const float* means = nullptr;
    const float* P     = nullptr;
    const float* wc    = nullptr;
    const float* v64a  = nullptr;
    const float* v64b  = nullptr;

    for (int i = 0; i < n_in; ++i) {
        const float* p = (const float*)d_in[i];
        switch (in_sizes[i]) {
            case 2097152: X = p; break;
            case 262144:  P = p; break;
            case 4096:    means = p; break;
            case 128:     wc = p; break;
            case 64:      if (!v64a) v64a = p; else v64b = p; break;
            default: break;
        }
    }
    if (!v64b) v64b = v64a;  // defensive
    float* out = (float*)d_out;

    bgm_prep_a<<<NK, DIM>>>(means, P, wc, v64a, v64b);
    bgm_argmax_kernel<<<NBLOCKS, NTHREADS>>>(X, P, out);
}

// round 12
// speedup vs baseline: 3.0641x; 3.0641x over previous
#include <cuda_runtime.h>
#include <cstdint>

// Problem constants (N=32768, D=64, K=64 per reference)
#define NPTS 32768
#define DIM 64
#define NK 64
#define ROWS_PER_BLOCK 64
#define NTHREADS 64            // 2 warps, e-split: warp0 quarters {0,3}, warp1 {1,2}
#define NBLOCKS (NPTS / ROWS_PER_BLOCK)   // 512

// Scratch (allocation-free rule: __device__ globals)
__device__ __align__(16) float d_negmuP[NK * DIM];  // -(means_k @ P_k), [K,D]
__device__ float d_Cpart[NK];                       // C without stick-breaking cumsum
__device__ float d_sdb[NK];                         // digamma(b)-digamma(a+b)

// ---------------------------------------------------------------------------
// NaN-proof helpers (identity on valid inputs).
// ---------------------------------------------------------------------------
static __device__ __forceinline__ double safe_log(double v) {
    v = fabs(v);
    if (v < 1e-300) v = 1e-300;
    return log(v);
}

// digamma in double; recurrence as independent divides (bit-identical order).
static __device__ __forceinline__ double digamma_d(double x) {
    if (!(x > 1e-6)) x = 1e-6;
    double r = 0.0;
    const double m = (x < 6.0) ? ceil(6.0 - x) : 0.0;   // <= 6 for x >= 0.5
#pragma unroll
    for (int j = 0; j < 6; ++j)
        if ((double)j < m) r -= 1.0 / (x + (double)j);
    x += m;
    const double inv  = 1.0 / x;
    const double inv2 = inv * inv;
    const double s = inv2 * (1.0 / 12.0
                   - inv2 * (1.0 / 120.0
                   - inv2 * (1.0 / 252.0
                   - inv2 * (1.0 / 240.0))));
    return r + log(x) - 0.5 * inv - s;
}

// ---------------------------------------------------------------------------
// Prep: 64 blocks (cluster k) x 64 threads (dimension i).
// ---------------------------------------------------------------------------
__global__ void bgm_prep_a(const float* __restrict__ means,
                           const float* __restrict__ P,
                           const float* __restrict__ wc,
                           const float* __restrict__ v64a,
                           const float* __restrict__ v64b) {
    const int k = blockIdx.x;
    const int i = threadIdx.x;
    __shared__ double sd[NK];

    const bool a_is_dof = (v64a[0] > 32.0f);   // dof in [65,114], mp in (0.5,10]
    const float* __restrict__ dof = a_is_dof ? v64a : v64b;
    const float* __restrict__ mp  = a_is_dof ? v64b : v64a;

    const double dofk = (double)dof[k];

    const double t  = digamma_d(0.5 * (dofk - (double)i));
    const double lg = safe_log((double)P[k * DIM * DIM + i * DIM + i]);
    sd[i] = lg + 0.5 * t;
    __syncthreads();

    {   // negmuP column i
        float s = 0.0f;
        for (int d = 0; d < DIM; ++d)
            s = fmaf(means[k * DIM + d], P[k * DIM * DIM + d * DIM + i], s);
        d_negmuP[k * DIM + i] = -s;
    }

    for (int off = 32; off > 0; off >>= 1) {
        if (i < off) sd[i] += sd[i + off];
        __syncthreads();
    }

    if (i == 0) {
        double mpk = (double)mp[k];
        if (!(mpk > 1e-6)) mpk = 1e-6;
        const double a  = (double)wc[k];
        const double b  = (double)wc[NK + k];
        const double ds = digamma_d(a + b);
        const double dga = digamma_d(a);
        const double dgb = digamma_d(b);
        double C = sd[0]
                 + 0.5 * (double)DIM * 0.69314718055994530942   // +0.5*D*log2
                 - 0.5 * (double)DIM * 1.8378770664093454836    // -0.5*D*log(2pi)
                 - 0.5 * (double)DIM * safe_log(dofk)
                 - 0.5 * (double)DIM / mpk
                 + dga - ds;
        d_Cpart[k] = (float)C;
        d_sdb[k]   = (float)(dgb - ds);
    }
}

// ---------------------------------------------------------------------------
// Packed f32x2 helpers (FFMA2 SASS — 2x scalar FFMA throughput on sm_103a)
// ---------------------------------------------------------------------------
static __device__ __forceinline__ unsigned long long ff2(
    unsigned long long a, unsigned long long b, unsigned long long c) {
    unsigned long long d;
    asm("fma.rn.f32x2 %0, %1, %2, %3;" : "=l"(d) : "l"(a), "l"(b), "l"(c));
    return d;
}
static __device__ __forceinline__ unsigned long long fadd2(
    unsigned long long a, unsigned long long b) {
    unsigned long long d;
    asm("add.rn.f32x2 %0, %1, %2;" : "=l"(d) : "l"(a), "l"(b));
    return d;
}
static __device__ __forceinline__ unsigned long long pack2(float x) {
    unsigned long long d;
    asm("mov.b64 %0, {%1, %1};" : "=l"(d) : "f"(x));
    return d;
}
static __device__ __forceinline__ void unpack2(unsigned long long v, float& lo, float& hi) {
    asm("mov.b64 {%0, %1}, %2;" : "=f"(lo), "=f"(hi) : "l"(v));
}

// cp.async 16B helpers
static __device__ __forceinline__ void cp16(uint32_t smem_addr, const void* gptr) {
    asm volatile("cp.async.cg.shared.global [%0], [%1], 16;" :: "r"(smem_addr), "l"(gptr));
}
static __device__ __forceinline__ void cp_commit() {
    asm volatile("cp.async.commit_group;");
}
template <int N>
static __device__ __forceinline__ void cp_wait() {
    asm volatile("cp.async.wait_group %0;" :: "n"(N));
}

// ---------------------------------------------------------------------------
// Main kernel: 512 blocks x 64 threads (2 warps), 64 rows/block.
// e-SPLIT: thread t owns rows (t%32, t%32+32); warp0 computes e-quarters
// {0,3}, warp1 {1,2} (triangular d-counts 80 each — balanced). Both warps
// share one double-buffered smem P_k. Per-(row,k) sq = warp0 half + warp1
// half, merged via a 1-k-deep pipelined smem exchange on the existing
// barriers. Warp0 tracks argmax (strict >, first-max). OUTPUT: float32.
// ---------------------------------------------------------------------------
__global__ __launch_bounds__(NTHREADS) void bgm_argmax_kernel(
    const float* __restrict__ X,
    const float* __restrict__ P,
    float* __restrict__ out) {

    __shared__ __align__(16) float Psm[2][DIM * DIM];                 // 2 x 16 KB
    __shared__ __align__(16) float Xsm[ROWS_PER_BLOCK * (DIM + 1)];   // padded
    __shared__ float Csm[NK];
    __shared__ float Sdb[NK];
    __shared__ float sqPart[2][2][32];   // [kbuf][rowhalf][lane] — warp1's halves

    const int tid  = threadIdx.x;
    const int wid  = tid >> 5;
    const int lane = tid & 31;
    const int row0 = blockIdx.x * ROWS_PER_BLOCK;

    // Stage X tile: 64 rows -> 1024 float4, 16 per thread.
    {
        const float4* __restrict__ Xg =
            reinterpret_cast<const float4*>(X + row0 * DIM);
        for (int i = tid; i < ROWS_PER_BLOCK * (DIM / 4); i += NTHREADS) {
            const float4 v = Xg[i];
            const int r = i >> 4;
            const int c = (i & 15) << 2;
            float* dst = &Xsm[r * (DIM + 1) + c];
            dst[0] = v.x; dst[1] = v.y; dst[2] = v.z; dst[3] = v.w;
        }
    }
    Sdb[tid] = d_sdb[tid];           // NTHREADS == NK
    __syncthreads();
    {   // Stick-breaking exclusive cumsum, bit-identical sequential fp32 order.
        float pre = 0.0f;
        for (int j = 0; j < tid; ++j) pre += Sdb[j];
        Csm[tid] = d_Cpart[tid] + pre;
    }

    // Prologue: stage P_0 into buffer 0 (16 float4 per thread)
    {
        const float4* src = reinterpret_cast<const float4*>(P);
        const uint32_t dst = (uint32_t)__cvta_generic_to_shared(&Psm[0][0]);
#pragma unroll
        for (int j = 0; j < 16; ++j)
            cp16(dst + (tid + j * NTHREADS) * 16, src + tid + j * NTHREADS);
        cp_commit();
    }

    // This warp's two e-quarters (d-work 80 each way: 16+64 vs 32+48).
    const int qA = (wid == 0) ? 0 : 1;
    const int qB = (wid == 0) ? 3 : 2;

    const int xb0 = lane * (DIM + 1);
    const int xb1 = (lane + 32) * (DIM + 1);
    float best0 = __int_as_float(0xff800000u), best1 = best0;
    int   arg0 = 0, arg1 = 0;
    float sqPrev0 = 0.0f, sqPrev1 = 0.0f;   // warp0's own halves for k-1

    const ulonglong2* __restrict__ nmAll =
        reinterpret_cast<const ulonglong2*>(d_negmuP);

    for (int k = 0; k < NK; ++k) {
        __syncthreads();   // (a) prev buffer free; warp1's k-1 partials visible
                           //     (also covers Xsm/Csm staging at k=0)

        // Warp0: merge halves for k-1 and update argmax.
        if (wid == 0 && k > 0) {
            const int pb = (k - 1) & 1;
            const float Ck = Csm[k - 1];
            const float s0 = sqPrev0 + sqPart[pb][0][lane];
            const float s1 = sqPrev1 + sqPart[pb][1][lane];
            const float w0 = fmaf(-0.5f, s0, Ck);
            const float w1 = fmaf(-0.5f, s1, Ck);
            if (w0 > best0) { best0 = w0; arg0 = k - 1; }
            if (w1 > best1) { best1 = w1; arg1 = k - 1; }
        }

        if (k + 1 < NK) {
            const float4* src = reinterpret_cast<const float4*>(P + (k + 1) * DIM * DIM);
            const uint32_t dst =
                (uint32_t)__cvta_generic_to_shared(&Psm[(k + 1) & 1][0]);
#pragma unroll
            for (int j = 0; j < 16; ++j)
                cp16(dst + (tid + j * NTHREADS) * 16, src + tid + j * NTHREADS);
            cp_commit();
            cp_wait<1>();   // P_k complete; P_{k+1} in flight
        } else {
            cp_wait<0>();
        }
        __syncthreads();    // (b) P_k visible to both warps

        const float* __restrict__ Pk = Psm[k & 1];
        unsigned long long s0 = 0ULL, s1 = 0ULL;   // running sq halves (f32x2)

#pragma unroll
        for (int h = 0; h < 2; ++h) {
            const int q    = (h == 0) ? qA : qB;
            const int dmax = 16 * (q + 1);         // triangular bound
            const int qoff = q << 4;

            unsigned long long a0[8], a1[8];
#pragma unroll
            for (int j = 0; j < 8; ++j) { a0[j] = 0ULL; a1[j] = 0ULL; }

#pragma unroll 4
            for (int d = 0; d < dmax; ++d) {
                const unsigned long long x0 = pack2(Xsm[xb0 + d]);
                const unsigned long long x1 = pack2(Xsm[xb1 + d]);
                const ulonglong2* __restrict__ pr =
                    reinterpret_cast<const ulonglong2*>(Pk + (d << 6) + qoff);
#pragma unroll
                for (int j = 0; j < 4; ++j) {
                    const ulonglong2 p = pr[j];    // LDS.128 broadcast: 2 f32x2
                    a0[2 * j]     = ff2(x0, p.x, a0[2 * j]);
                    a0[2 * j + 1] = ff2(x0, p.y, a0[2 * j + 1]);
                    a1[2 * j]     = ff2(x1, p.x, a1[2 * j]);
                    a1[2 * j + 1] = ff2(x1, p.y, a1[2 * j + 1]);
                }
            }

            // Quarter epilogue: s += (acc + negmuP_quarter)^2
            const ulonglong2* __restrict__ nm = nmAll + (k << 4) + (q << 2);
#pragma unroll
            for (int j = 0; j < 4; ++j) {
                const ulonglong2 m = nm[j];
                const unsigned long long e0a = fadd2(a0[2 * j],     m.x);
                const unsigned long long e0b = fadd2(a0[2 * j + 1], m.y);
                const unsigned long long e1a = fadd2(a1[2 * j],     m.x);
                const unsigned long long e1b = fadd2(a1[2 * j + 1], m.y);
                s0 = ff2(e0a, e0a, s0);
                s0 = ff2(e0b, e0b, s0);
                s1 = ff2(e1a, e1a, s1);
                s1 = ff2(e1b, e1b, s1);
            }
        }

        float l0, h0, l1, h1;
        unpack2(s0, l0, h0);
        unpack2(s1, l1, h1);
        const float half0 = l0 + h0;   // this warp's sq half, row lane
        const float half1 = l1 + h1;   // row lane+32

        if (wid == 1) {
            sqPart[k & 1][0][lane] = half0;
            sqPart[k & 1][1][lane] = half1;
        } else {
            sqPrev0 = half0;
            sqPrev1 = half1;
        }
    }

    __syncthreads();   // warp1's k=63 partials visible
    if (wid == 0) {
        const int pb = (NK - 1) & 1;
        const float Ck = Csm[NK - 1];
        const float s0 = sqPrev0 + sqPart[pb][0][lane];
        const float s1 = sqPrev1 + sqPart[pb][1][lane];
        const float w0 = fmaf(-0.5f, s0, Ck);
        const float w1 = fmaf(-0.5f, s1, Ck);
        if (w0 > best0) { best0 = w0; arg0 = NK - 1; }
        if (w1 > best1) { best1 = w1; arg1 = NK - 1; }
        out[row0 + lane]      = (float)arg0;
        out[row0 + lane + 32] = (float)arg1;
    }
}

// ---------------------------------------------------------------------------
// Launch. Inputs identified by ELEMENT COUNT; dof/mp disambiguated on device.
// Output: float32 index values [N].
// ---------------------------------------------------------------------------
extern "C" void kernel_launch(void* const* d_in, const int* in_sizes, int n_in,
                              void* d_out, int out_size) {
    (void)out_size;
    const float* X     = nullptr;
    const float* means = nullptr;
    const float* P     = nullptr;
    const float* wc    = nullptr;
    const float* v64a  = nullptr;
    const float* v64b  = nullptr;

    for (int i = 0; i < n_in; ++i) {
        const float* p = (const float*)d_in[i];
        switch (in_sizes[i]) {
            case 2097152: X = p; break;
            case 262144:  P = p; break;
            case 4096:    means = p; break;
            case 128:     wc = p; break;
            case 64:      if (!v64a) v64a = p; else v64b = p; break;
            default: break;
        }
    }
    if (!v64b) v64b = v64a;  // defensive
    float* out = (float*)d_out;

    bgm_prep_a<<<NK, DIM>>>(means, P, wc, v64a, v64b);
    bgm_argmax_kernel<<<NBLOCKS, NTHREADS>>>(X, P, out);
}